// round 12
// baseline (speedup 1.0000x reference)
#include <cuda_runtime.h>
#include <cuda_bf16.h>
#include <cstdint>

#define BB 64
#define TT 2048
#define EE 256
#define AA 128
#define PP 128
#define RR 1024
#define DD 1024
#define HH 256
#define FF 32
#define KK 31
#define PAD 15
#define NEG_INF (-1e30f)

#define NBLK 444            // 148 SMs x 3 CTAs
#define NTHR 256
#define NT   (NBLK * NTHR)
#define NEBLK 252           // energies sub-group: bids 192..443

typedef unsigned long long ull;

// ---------------- scratch ----------------
__device__ float g_part[6 * BB * 4096];   // split-K partials (6MB)
__device__ float g_ah[BB * RR];
__device__ float g_ac[BB * RR];
__device__ float g_dh[BB * DD];
__device__ float g_dc[BB * DD];
__device__ float g_pq[BB * AA];
__device__ float g_energy[BB * TT];
__device__ float g_bm[BB * 8];
__device__ float g_bs[BB * 8];
__device__ float g_ctx_part[BB * 8 * EE];
__device__ float g_ctx[BB * EE];
__device__ int   g_maskmode;

// tree barrier state (leaf counters padded to 128B to avoid L2 same-line serialization)
__device__ unsigned g_leaf[32 * 32];
__device__ unsigned g_root;
__device__ volatile unsigned g_bar_sense;
__device__ unsigned g_leaf2[32 * 32];
__device__ unsigned g_root2;
__device__ volatile unsigned g_bar2_sense;

__device__ __forceinline__ float tanhfast(float x) {
    float y; asm("tanh.approx.f32 %0, %1;" : "=f"(y) : "f"(x)); return y;
}
__device__ __forceinline__ float sigfast(float x) {
    return 0.5f * tanhfast(0.5f * x) + 0.5f;
}
__device__ __forceinline__ ull pack2(float lo, float hi) {
    ull r; asm("mov.b64 %0, {%1, %2};" : "=l"(r) : "f"(lo), "f"(hi)); return r;
}
__device__ __forceinline__ ull fma2(ull a, ull b, ull c) {
    ull r; asm("fma.rn.f32x2 %0, %1, %2, %3;" : "=l"(r) : "l"(a), "l"(b), "l"(c)); return r;
}
__device__ __forceinline__ float2 unpack2(ull v) {
    float2 f; asm("mov.b64 {%0, %1}, %2;" : "=f"(f.x), "=f"(f.y) : "l"(v)); return f;
}

// ---------------- two-level grid barrier (all 444 blocks) ------------------
// leaf l (=bid&31) has count: 444 = 13*32 + 28  -> l<28 ? 14 : 13
__device__ __forceinline__ void gridbar(unsigned& sense, int bid) {
    __syncthreads();
    if (threadIdx.x == 0) {
        unsigned ns = sense ^ 1u;
        int leaf = bid & 31;
        unsigned lcnt = (leaf < 28) ? 14u : 13u;
        __threadfence();
        unsigned prev = atomicAdd(&g_leaf[leaf * 32], 1u);
        if (prev == lcnt - 1u) {
            atomicExch(&g_leaf[leaf * 32], 0u);
            unsigned pr = atomicAdd(&g_root, 1u);
            if (pr == 31u) {
                atomicExch(&g_root, 0u);
                __threadfence();
                g_bar_sense = ns;
            }
        }
        while (g_bar_sense != ns) __nanosleep(32);
        __threadfence();
        sense = ns;
    }
    __syncthreads();
}

// ---------------- two-level sub barrier (252 energies blocks) --------------
// 252 = 7*32 + 28 -> l<28 ? 8 : 7
__device__ __forceinline__ void gridbar2(unsigned& sense2, int lbid) {
    __syncthreads();
    if (threadIdx.x == 0) {
        unsigned ns = sense2 ^ 1u;
        int leaf = lbid & 31;
        unsigned lcnt = (leaf < 28) ? 8u : 7u;
        __threadfence();
        unsigned prev = atomicAdd(&g_leaf2[leaf * 32], 1u);
        if (prev == lcnt - 1u) {
            atomicExch(&g_leaf2[leaf * 32], 0u);
            unsigned pr = atomicAdd(&g_root2, 1u);
            if (pr == 31u) {
                atomicExch(&g_root2, 0u);
                __threadfence();
                g_bar2_sense = ns;
            }
        }
        while (g_bar2_sense != ns) __nanosleep(32);
        __threadfence();
        sense2 = ns;
    }
    __syncthreads();
}

// ---------------- shared memory union ----------------
struct GeS { ull As2[3][16][64]; float Wsf[3][16][64]; };     // 36.9 KB
struct EnS {
    float aw0[288]; float aw1[288]; float pq[AA]; float wv[AA];
    ulonglong2 wl2[2][KK][8]; ulonglong2 wlfc2[AA][8]; float red[256];
};
struct CxS { float w[256]; float4 r4[256]; };
union SMemU { GeS ge; EnS en; CxS cx; };

struct Seg { const float* A; const float* W; int lda; int ldw; int K; };

// ---------------- 64x64 tile GEMM over chunk range [cbeg,cend), pipelined ----
__device__ void gemm_tile(const Seg* segs, int j0, int cbeg, int cend,
                          float* dst, int ldo, GeS& sh) {
    int tid = threadIdx.x;
    int tx = tid & 15, ty = tid >> 4;
    int ml = tid & 63, kk4 = tid >> 6;
    int n0 = segs[0].K >> 4;
    int n1 = segs[1].K >> 4;

    ull acc[4][2];
#pragma unroll
    for (int i = 0; i < 4; i++) { acc[i][0] = 0ull; acc[i][1] = 0ull; }

    auto fetch = [&](int c, float4& a4, float4& w4) {
        int cc = c, sg = 0;
        if (cc >= n0) {
            cc -= n0; sg = 1;
            if (cc >= n1) { cc -= n1; sg = 2; }
        }
        const Seg& S = segs[sg];
        int k = cc * 16 + kk4 * 4;
        a4 = *(const float4*)(S.A + (size_t)ml * S.lda + k);
        w4 = *(const float4*)(S.W + (size_t)(j0 + ml) * S.ldw + k);
    };
    auto store = [&](int buf, const float4& a4, const float4& w4) {
        int kb = kk4 * 4;
        sh.As2[buf][kb + 0][ml] = pack2(a4.x, a4.x);
        sh.As2[buf][kb + 1][ml] = pack2(a4.y, a4.y);
        sh.As2[buf][kb + 2][ml] = pack2(a4.z, a4.z);
        sh.As2[buf][kb + 3][ml] = pack2(a4.w, a4.w);
        sh.Wsf[buf][kb + 0][ml] = w4.x;
        sh.Wsf[buf][kb + 1][ml] = w4.y;
        sh.Wsf[buf][kb + 2][ml] = w4.z;
        sh.Wsf[buf][kb + 3][ml] = w4.w;
    };
    auto compute = [&](int buf) {
#pragma unroll
        for (int kk = 0; kk < 16; kk++) {
            const ulonglong2* ar = (const ulonglong2*)&sh.As2[buf][kk][ty * 4];
            ulonglong2 a01 = ar[0];
            ulonglong2 a23 = ar[1];
            ulonglong2 w = *(const ulonglong2*)&sh.Wsf[buf][kk][tx * 4];
            acc[0][0] = fma2(a01.x, w.x, acc[0][0]); acc[0][1] = fma2(a01.x, w.y, acc[0][1]);
            acc[1][0] = fma2(a01.y, w.x, acc[1][0]); acc[1][1] = fma2(a01.y, w.y, acc[1][1]);
            acc[2][0] = fma2(a23.x, w.x, acc[2][0]); acc[2][1] = fma2(a23.x, w.y, acc[2][1]);
            acc[3][0] = fma2(a23.y, w.x, acc[3][0]); acc[3][1] = fma2(a23.y, w.y, acc[3][1]);
        }
    };

    int nch = cend - cbeg;
    float4 Aa, Wa, Ab, Wb;
    {
        float4 a, w;
        fetch(cbeg, a, w); store(0, a, w);
        if (nch > 1) { fetch(cbeg + 1, a, w); store(1, a, w); }
    }
    if (nch > 2) fetch(cbeg + 2, Aa, Wa);
    if (nch > 3) fetch(cbeg + 3, Ab, Wb);
    __syncthreads();

    for (int i = 0; i < nch; i++) {
        compute(i % 3);
        __syncthreads();
        if (i + 2 < nch) {
            store((i + 2) % 3, Aa, Wa);
            Aa = Ab; Wa = Wb;
            if (i + 4 < nch) fetch(cbeg + i + 4, Ab, Wb);
        }
    }

#pragma unroll
    for (int i = 0; i < 4; i++) {
        int m = ty * 4 + i;
        float2 r0 = unpack2(acc[i][0]);
        float2 r1 = unpack2(acc[i][1]);
        float4 v = make_float4(r0.x, r0.y, r1.x, r1.y);
        *(float4*)(dst + (size_t)m * ldo + j0 + tx * 4) = v;
    }
}

// ---------------- params ----------------
struct Params {
    const float *last_frame, *att_h, *att_c, *att_w, *att_w_cum, *att_ctx,
                *dec_h, *dec_c, *memory, *pm,
                *W_ih_a, *W_hh_a, *b_ih_a, *b_hh_a,
                *W_q, *W_v, *W_loc, *W_lfc,
                *W_ih_d, *W_hh_d, *b_ih_d, *b_hh_d,
                *W_proj, *b_proj, *W_gate, *b_gate;
    const void* mask;
    float *out, *stop_out, *w_out;
};

// ---------------- helper: LSTM pointwise over all elements ----------------
__device__ void lstm_phase(const float* part, int nsplit,
                           const float* b1, const float* b2,
                           const float* c_in, float* h_out, float* c_out, int gtid) {
    for (int idx = gtid; idx < BB * 1024; idx += NT) {
        int b = idx >> 10, r = idx & 1023;
        size_t base = (size_t)b * 4096;
        float g0 = b1[r]        + b2[r];
        float g1 = b1[1024 + r] + b2[1024 + r];
        float g2 = b1[2048 + r] + b2[2048 + r];
        float g3 = b1[3072 + r] + b2[3072 + r];
        for (int p = 0; p < nsplit; p++) {
            const float* pp = part + (size_t)p * BB * 4096 + base + r;
            g0 += pp[0];
            g1 += pp[1024];
            g2 += pp[2048];
            g3 += pp[3072];
        }
        float c  = c_in[idx];
        float c2 = sigfast(g1) * c + sigfast(g0) * tanhfast(g2);
        float h2 = sigfast(g3) * tanhfast(c2);
        c_out[idx] = c2;
        h_out[idx] = h2;
    }
}

// ---------------- the mono kernel (3 blocks/SM) ----------------
__global__ __launch_bounds__(NTHR, 3) void mono_k(Params p) {
    __shared__ SMemU sm;
    int tid = threadIdx.x;
    int bid = blockIdx.x;
    int gtid = bid * NTHR + tid;
    unsigned sense = 0, sense2 = 0;
    if (tid == 0) { sense = g_bar_sense; sense2 = g_bar2_sense; }

    // ================= Phase A: attention-gate GEMM (6-way splitK) =========
    if (bid < 384) {
        Seg sa[3] = {
            { p.last_frame, p.W_ih_a,      PP, PP + EE, PP },
            { p.att_ctx,    p.W_ih_a + PP, EE, PP + EE, EE },
            { p.att_h,      p.W_hh_a,      RR, RR,      RR }
        };
        int jt = bid & 63;
        int sp = bid >> 6;      // 0..5
        int cb = (88 * sp) / 6;
        int ce = (88 * (sp + 1)) / 6;
        gemm_tile(sa, jt * 64, cb, ce,
                  g_part + (size_t)sp * BB * 4096, 4096, sm.ge);
    } else if (bid == 440) {
        const unsigned int* mw = (const unsigned int*)p.mask;
        int n01 = 0, nf = 0;
        for (int i = tid; i < 4096; i += NTHR) {
            unsigned v = mw[i];
            n01 |= (v > 1u);
            nf  |= (v != 0u && v != 0x3F800000u);
        }
        int a  = __syncthreads_or(n01);
        int bf = __syncthreads_or(nf);
        if (tid == 0) g_maskmode = a ? (bf ? 2 : 1) : 0;
    }
    gridbar(sense, bid);

    // ================= Phase B: attention LSTM pointwise ====================
    lstm_phase(g_part, 6, p.b_ih_a, p.b_hh_a, p.att_c, g_ah, g_ac, gtid);
    gridbar(sense, bid);

    // ================= Phase CD: decoder GEMM (K=2048)  ||  pq + energies ===
    if (bid < 192) {
        Seg sd[3] = {
            { g_ah,    p.W_ih_d, RR, RR + EE, RR },
            { p.dec_h, p.W_hh_d, DD, DD,      DD },
            { g_ah,    p.W_ih_d, RR, RR + EE, 0 }   // dummy
        };
        int jt = bid & 63;
        int sp = bid >> 6;      // 0..2; 128 chunks -> thirds
        int cb = (128 * sp) / 3;
        int ce = (128 * (sp + 1)) / 3;
        gemm_tile(sd, jt * 64, cb, ce,
                  g_part + (size_t)sp * BB * 4096, 4096, sm.ge);
    } else {
        int lbid = bid - 192;   // 0..251
        // ---- pq: warp dots over the energies sub-grid ----
        {
            int wid = lbid * (NTHR / 32) + (tid >> 5);
            int lane = tid & 31;
            for (int j = wid; j < BB * AA; j += NEBLK * (NTHR / 32)) {
                int m = j >> 7, n = j & 127;
                const float4* a = (const float4*)(g_ah + (size_t)m * RR);
                const float4* w = (const float4*)(p.W_q + (size_t)n * RR);
                float s = 0.f;
#pragma unroll
                for (int i = 0; i < 8; i++) {
                    float4 x = a[lane + 32 * i];
                    float4 y = w[lane + 32 * i];
                    s += x.x * y.x + x.y * y.y + x.z * y.z + x.w * y.w;
                }
#pragma unroll
                for (int off = 16; off > 0; off >>= 1) s += __shfl_xor_sync(0xFFFFFFFFu, s, off);
                if (lane == 0) g_pq[j] = s;
            }
        }
        gridbar2(sense2, lbid);   // pq visible to all 252 energies blocks

        // ---- energies: stage weights once, then up to 3 jobs ----
        for (int i = tid; i < 2 * KK * 16; i += NTHR) {
            int c = i / (KK * 16);
            int r = i % (KK * 16);
            int k = r / 16, fp = r % 16;
            float lo = p.W_loc[(2 * fp + 0) * (2 * KK) + c * KK + k];
            float hi = p.W_loc[(2 * fp + 1) * (2 * KK) + c * KK + k];
            ((ull*)sm.en.wl2)[c * KK * 16 + k * 16 + fp] = pack2(lo, hi);
        }
        for (int i = tid; i < AA * 8; i += NTHR)
            ((ulonglong2*)sm.en.wlfc2)[i] = ((const ulonglong2*)p.W_lfc)[i];
        if (tid < AA) sm.en.wv[tid] = p.W_v[tid];
        int mm = g_maskmode;

        for (int it = 0; it < 3; it++) {
            int job = lbid + it * NEBLK;
            if (job >= 512) break;
            int b = job >> 3, tc = job & 7;
            int t0 = tc * 256;
            int t = t0 + tid;
            __syncthreads();
            for (int i = tid; i < 286; i += NTHR) {
                int gidx = t0 - PAD + i;
                bool inb = (gidx >= 0 && gidx < TT);
                sm.en.aw0[i] = inb ? p.att_w[(size_t)b * TT + gidx] : 0.f;
                sm.en.aw1[i] = inb ? p.att_w_cum[(size_t)b * TT + gidx] : 0.f;
            }
            if (tid < AA) sm.en.pq[tid] = g_pq[b * AA + tid];
            __syncthreads();

            ull locf2[16];
#pragma unroll
            for (int i = 0; i < 16; i++) locf2[i] = 0ull;
            for (int k = 0; k < KK; k++) {
                ull a0 = pack2(sm.en.aw0[tid + k], sm.en.aw0[tid + k]);
                ull a1 = pack2(sm.en.aw1[tid + k], sm.en.aw1[tid + k]);
#pragma unroll
                for (int i = 0; i < 8; i++) {
                    ulonglong2 w0 = sm.en.wl2[0][k][i];
                    ulonglong2 w1 = sm.en.wl2[1][k][i];
                    locf2[2 * i]     = fma2(a0, w0.x, locf2[2 * i]);
                    locf2[2 * i + 1] = fma2(a0, w0.y, locf2[2 * i + 1]);
                    locf2[2 * i]     = fma2(a1, w1.x, locf2[2 * i]);
                    locf2[2 * i + 1] = fma2(a1, w1.y, locf2[2 * i + 1]);
                }
            }

            const float4* pmrow4 = (const float4*)(p.pm + ((size_t)b * TT + t) * AA);
            float e = 0.f;
#pragma unroll 1
            for (int a = 0; a < AA; a += 4) {
                float4 pv = pmrow4[a >> 2];
#pragma unroll
                for (int half = 0; half < 2; half++) {
                    int aa = a + 2 * half;
                    float p0 = half ? pv.z : pv.x;
                    float p1 = half ? pv.w : pv.y;
                    ull ac0 = 0ull, ac1 = 0ull, ac2 = 0ull, ac3 = 0ull;
#pragma unroll
                    for (int i = 0; i < 8; i++) {
                        ulonglong2 w0 = sm.en.wlfc2[aa][i];
                        ulonglong2 w1 = sm.en.wlfc2[aa + 1][i];
                        ac0 = fma2(locf2[2 * i],     w0.x, ac0);
                        ac1 = fma2(locf2[2 * i + 1], w0.y, ac1);
                        ac2 = fma2(locf2[2 * i],     w1.x, ac2);
                        ac3 = fma2(locf2[2 * i + 1], w1.y, ac3);
                    }
                    float2 f0 = unpack2(ac0), f1 = unpack2(ac1);
                    float2 f2 = unpack2(ac2), f3 = unpack2(ac3);
                    float la0 = (f0.x + f0.y) + (f1.x + f1.y);
                    float la1 = (f2.x + f2.y) + (f3.x + f3.y);
                    float x0 = sm.en.pq[aa] + p0 + la0;
                    float x1 = sm.en.pq[aa + 1] + p1 + la1;
                    e += tanhfast(x0) * sm.en.wv[aa];
                    e += tanhfast(x1) * sm.en.wv[aa + 1];
                }
            }

            size_t mi = (size_t)b * TT + t;
            bool masked;
            if (mm == 0)      masked = (((const int*)p.mask)[mi] != 0);
            else if (mm == 1) masked = (((const float*)p.mask)[mi] != 0.f);
            else              masked = (((const unsigned char*)p.mask)[mi] != 0);
            e = masked ? NEG_INF : e;
            g_energy[mi] = e;

            sm.en.red[tid] = e; __syncthreads();
            for (int s = 128; s > 0; s >>= 1) {
                if (tid < s) sm.en.red[tid] = fmaxf(sm.en.red[tid], sm.en.red[tid + s]);
                __syncthreads();
            }
            float Mc = sm.en.red[0]; __syncthreads();
            sm.en.red[tid] = __expf(e - Mc); __syncthreads();
            for (int s = 128; s > 0; s >>= 1) {
                if (tid < s) sm.en.red[tid] += sm.en.red[tid + s];
                __syncthreads();
            }
            if (tid == 0) {
                g_bm[b * 8 + tc] = Mc;
                g_bs[b * 8 + tc] = sm.en.red[0];
            }
        }
    }
    gridbar(sense, bid);

    // ================= Phase E: context partials + weights output ==========
    for (int it = 0; it < 2; it++) {
        int job = bid + it * NBLK;
        if (job >= 512) break;
        int b = job >> 3, tc = job & 7;
        int t0 = tc * 256;
        float M = -3.0e38f;
#pragma unroll
        for (int c = 0; c < 8; c++) M = fmaxf(M, g_bm[b * 8 + c]);
        float S = 0.f;
#pragma unroll
        for (int c = 0; c < 8; c++) S += g_bs[b * 8 + c] * __expf(g_bm[b * 8 + c] - M);
        float inv = 1.0f / S;

        __syncthreads();
        float w = __expf(g_energy[(size_t)b * TT + t0 + tid] - M) * inv;
        sm.cx.w[tid] = w;
        p.w_out[(size_t)b * TT + t0 + tid] = w;
        __syncthreads();

        // vectorized: thread (rr, ee) handles cols 4*ee..4*ee+3, rows rr*64..rr*64+63
        int rr = tid >> 6;        // 0..3
        int ee = tid & 63;        // 0..63
        const ulonglong2* mbase =
            (const ulonglong2*)(p.memory + ((size_t)b * TT + t0) * EE) + ee;
        ull a01 = 0ull, a23 = 0ull;
#pragma unroll 4
        for (int i = 0; i < 64; i++) {
            int row = rr * 64 + i;
            float wv = sm.cx.w[row];
            ulonglong2 mv = mbase[(size_t)row * 64];
            ull wv2 = pack2(wv, wv);
            a01 = fma2(wv2, mv.x, a01);
            a23 = fma2(wv2, mv.y, a23);
        }
        __syncthreads();
        {
            float2 r0 = unpack2(a01), r1 = unpack2(a23);
            sm.cx.r4[tid] = make_float4(r0.x, r0.y, r1.x, r1.y);
        }
        __syncthreads();
        if (tid < 64) {
            float4 s0 = sm.cx.r4[tid], s1 = sm.cx.r4[tid + 64];
            float4 s2 = sm.cx.r4[tid + 128], s3 = sm.cx.r4[tid + 192];
            float4 s;
            s.x = (s0.x + s1.x) + (s2.x + s3.x);
            s.y = (s0.y + s1.y) + (s2.y + s3.y);
            s.z = (s0.z + s1.z) + (s2.z + s3.z);
            s.w = (s0.w + s1.w) + (s2.w + s3.w);
            *(float4*)&g_ctx_part[((size_t)b * 8 + tc) * EE + tid * 4] = s;
        }
        __syncthreads();
    }
    gridbar(sense, bid);

    // ================= Phase F: context reduce =============================
    for (int idx = gtid; idx < BB * EE; idx += NT) {
        int b = idx >> 8, e = idx & 255;
        float s = 0.f;
#pragma unroll
        for (int q = 0; q < 8; q++) s += g_ctx_part[((size_t)b * 8 + q) * EE + e];
        g_ctx[idx] = s;
    }
    gridbar(sense, bid);

    // ================= Phase G3: ctx contribution to decoder gates =========
    if (bid < 128) {
        Seg sc[3] = {
            { g_ctx, p.W_ih_d + RR, EE, RR + EE, EE },
            { g_ctx, p.W_ih_d + RR, EE, RR + EE, 0 },   // dummy
            { g_ctx, p.W_ih_d + RR, EE, RR + EE, 0 }    // dummy
        };
        int jt = bid & 63;
        int sp = bid >> 6;      // 0..1; 16 chunks -> (0,8),(8,16)
        gemm_tile(sc, jt * 64, sp * 8, sp * 8 + 8,
                  g_part + (size_t)(3 + sp) * BB * 4096, 4096, sm.ge);
    }
    gridbar(sense, bid);

    // ================= Phase H: decoder LSTM pointwise =====================
    lstm_phase(g_part, 5, p.b_ih_d, p.b_hh_d, p.dec_c, g_dh, g_dc, gtid);
    gridbar(sense, bid);

    // ================= Phase I: projection + stop heads ====================
    {
        int wid = gtid >> 5, lane = gtid & 31;
        for (int j = wid; j < BB * HH + BB; j += NT / 32) {
            bool is_stop = (j >= BB * HH);
            int m, h;
            const float4* w;
            if (!is_stop) {
                m = j >> 8; h = j & 255;
                w = (const float4*)(p.W_proj + (size_t)h * (DD + EE));
            } else {
                m = j - BB * HH;
                h = 0;
                w = (const float4*)p.W_gate;
            }
            const float4* a1 = (const float4*)(g_dh + (size_t)m * DD);
            const float4* a2 = (const float4*)(g_ctx + (size_t)m * EE);
            float s = 0.f;
#pragma unroll
            for (int i = 0; i < 8; i++) {
                float4 x = a1[lane + 32 * i];
                float4 y = w[lane + 32 * i];
                s += x.x * y.x + x.y * y.y + x.z * y.z + x.w * y.w;
            }
#pragma unroll
            for (int i = 0; i < 2; i++) {
                float4 x = a2[lane + 32 * i];
                float4 y = w[256 + lane + 32 * i];
                s += x.x * y.x + x.y * y.y + x.z * y.z + x.w * y.w;
            }
#pragma unroll
            for (int off = 16; off > 0; off >>= 1) s += __shfl_xor_sync(0xFFFFFFFFu, s, off);
            if (lane == 0) {
                if (!is_stop) p.out[j] = s + p.b_proj[h];
                else          p.stop_out[m] = s + p.b_gate[0];
            }
        }
    }
}

// ---------------- launch ----------------
extern "C" void kernel_launch(void* const* d_in, const int* in_sizes, int n_in,
                              void* d_out, int out_size) {
    Params p;
    p.last_frame = (const float*)d_in[0];
    p.att_h      = (const float*)d_in[1];
    p.att_c      = (const float*)d_in[2];
    p.att_w      = (const float*)d_in[3];
    p.att_w_cum  = (const float*)d_in[4];
    p.att_ctx    = (const float*)d_in[5];
    p.dec_h      = (const float*)d_in[6];
    p.dec_c      = (const float*)d_in[7];
    p.memory     = (const float*)d_in[8];
    p.pm         = (const float*)d_in[9];
    p.W_ih_a     = (const float*)d_in[10];
    p.W_hh_a     = (const float*)d_in[11];
    p.b_ih_a     = (const float*)d_in[12];
    p.b_hh_a     = (const float*)d_in[13];
    p.W_q        = (const float*)d_in[14];
    p.W_v        = (const float*)d_in[15];
    p.W_loc      = (const float*)d_in[16];
    p.W_lfc      = (const float*)d_in[17];
    p.W_ih_d     = (const float*)d_in[18];
    p.W_hh_d     = (const float*)d_in[19];
    p.b_ih_d     = (const float*)d_in[20];
    p.b_hh_d     = (const float*)d_in[21];
    p.W_proj     = (const float*)d_in[22];
    p.b_proj     = (const float*)d_in[23];
    p.W_gate     = (const float*)d_in[24];
    p.b_gate     = (const float*)d_in[25];
    p.mask       = d_in[26];

    float* out = (float*)d_out;
    p.out      = out;
    p.stop_out = out + BB * HH;
    p.w_out    = out + BB * HH + BB;

    mono_k<<<NBLK, NTHR>>>(p);
}

// round 14
// speedup vs baseline: 1.2166x; 1.2166x over previous
#include <cuda_runtime.h>
#include <cuda_bf16.h>
#include <cstdint>

#define BB 64
#define TT 2048
#define EE 256
#define AA 128
#define PP 128
#define RR 1024
#define DD 1024
#define HH 256
#define FF 32
#define KK 31
#define PAD 15
#define NEG_INF (-1e30f)

#define NBLK 444            // 148 SMs x 3 CTAs
#define NTHR 256
#define NT   (NBLK * NTHR)
#define NEBLK 252           // energies sub-group: bids 192..443

typedef unsigned long long ull;

// ---------------- scratch ----------------
__device__ float g_part[12 * BB * 4096];  // split-K partials (12MB)
__device__ float g_ah[BB * RR];
__device__ float g_ac[BB * RR];
__device__ float g_dh[BB * DD];
__device__ float g_dc[BB * DD];
__device__ float g_pq[BB * AA];
__device__ float g_energy[BB * TT];
__device__ float g_bm[BB * 8];
__device__ float g_bs[BB * 8];
__device__ float g_ctx_part[BB * 8 * EE];
__device__ float g_ctx[BB * EE];
__device__ int   g_maskmode;
__device__ unsigned g_job1;          // energies steal counter
__device__ unsigned g_job2;          // ctx-partial steal counter

// tree barrier state
__device__ unsigned g_leaf[32 * 32];
__device__ unsigned g_root;
__device__ volatile unsigned g_bar_sense;
__device__ unsigned g_leaf2[32 * 32];
__device__ unsigned g_root2;
__device__ volatile unsigned g_bar2_sense;

__device__ __forceinline__ float tanhfast(float x) {
    float y; asm("tanh.approx.f32 %0, %1;" : "=f"(y) : "f"(x)); return y;
}
__device__ __forceinline__ float sigfast(float x) {
    return 0.5f * tanhfast(0.5f * x) + 0.5f;
}
__device__ __forceinline__ ull pack2(float lo, float hi) {
    ull r; asm("mov.b64 %0, {%1, %2};" : "=l"(r) : "f"(lo), "f"(hi)); return r;
}
__device__ __forceinline__ ull fma2(ull a, ull b, ull c) {
    ull r; asm("fma.rn.f32x2 %0, %1, %2, %3;" : "=l"(r) : "l"(a), "l"(b), "l"(c)); return r;
}
__device__ __forceinline__ float2 unpack2(ull v) {
    float2 f; asm("mov.b64 {%0, %1}, %2;" : "=f"(f.x), "=f"(f.y) : "l"(v)); return f;
}

// ---------------- two-level grid barrier (all 444 blocks) ------------------
__device__ __forceinline__ void gridbar(unsigned& sense, int bid) {
    __syncthreads();
    if (threadIdx.x == 0) {
        unsigned ns = sense ^ 1u;
        int leaf = bid & 31;
        unsigned lcnt = (leaf < 28) ? 14u : 13u;   // 444 = 28*14 + 4*13
        __threadfence();
        unsigned prev = atomicAdd(&g_leaf[leaf * 32], 1u);
        if (prev == lcnt - 1u) {
            atomicExch(&g_leaf[leaf * 32], 0u);
            unsigned pr = atomicAdd(&g_root, 1u);
            if (pr == 31u) {
                atomicExch(&g_root, 0u);
                __threadfence();
                g_bar_sense = ns;
            }
        }
        while (g_bar_sense != ns) __nanosleep(32);
        __threadfence();
        sense = ns;
    }
    __syncthreads();
}

// ---------------- two-level sub barrier (252 energies blocks) --------------
__device__ __forceinline__ void gridbar2(unsigned& sense2, int lbid) {
    __syncthreads();
    if (threadIdx.x == 0) {
        unsigned ns = sense2 ^ 1u;
        int leaf = lbid & 31;
        unsigned lcnt = (leaf < 28) ? 8u : 7u;     // 252 = 28*8 + 4*7
        __threadfence();
        unsigned prev = atomicAdd(&g_leaf2[leaf * 32], 1u);
        if (prev == lcnt - 1u) {
            atomicExch(&g_leaf2[leaf * 32], 0u);
            unsigned pr = atomicAdd(&g_root2, 1u);
            if (pr == 31u) {
                atomicExch(&g_root2, 0u);
                __threadfence();
                g_bar2_sense = ns;
            }
        }
        while (g_bar2_sense != ns) __nanosleep(32);
        __threadfence();
        sense2 = ns;
    }
    __syncthreads();
}

// ---------------- shared memory union ----------------
struct GeS { float As[3][16][64]; float Ws[3][16][128]; };   // 12KB + 24KB = 36KB
struct EnS {
    float aw0[288]; float aw1[288]; float pq[AA]; float wv[AA];
    ulonglong2 wl2[2][KK][8]; ulonglong2 wlfc2[AA][8]; float red[256];
    int job;
};
struct CxS { float w[256]; float4 r4[256]; int job; };
union SMemU { GeS ge; EnS en; CxS cx; };

struct Seg { const float* A; const float* W; int lda; int ldw; int K; };

// ---------------- 64x128 tile GEMM over chunk range [cbeg,cend) ------------
// M-pair packing: A stored plain in smem, consecutive M loaded as f32x2 pairs;
// W duplicated on the fly via 4 ALU packs. 32 FMAs per 48B of LDS.
__device__ void gemm_tile(const Seg* segs, int j0, int cbeg, int cend,
                          float* dst, int ldo, GeS& sh) {
    int tid = threadIdx.x;
    int tx = tid & 31;        // N groups of 4 -> 128 N
    int ty = tid >> 5;        // 0..7, M groups of 8 -> 64 M
    int ml  = tid & 63, kk4 = tid >> 6;   // A loader: 64 rows x 4 kk-groups
    int wml = tid & 127, kh = tid >> 7;   // W loader: 128 rows x 2 k-halves
    int n0 = segs[0].K >> 4;
    int n1 = segs[1].K >> 4;

    ull acc[4][4];
#pragma unroll
    for (int i = 0; i < 4; i++)
#pragma unroll
        for (int j = 0; j < 4; j++) acc[i][j] = 0ull;

    auto fetch = [&](int c, float4& a4, float4& w4a, float4& w4b) {
        int cc = c, sg = 0;
        if (cc >= n0) {
            cc -= n0; sg = 1;
            if (cc >= n1) { cc -= n1; sg = 2; }
        }
        const Seg& S = segs[sg];
        int k0 = cc * 16;
        a4  = *(const float4*)(S.A + (size_t)ml * S.lda + k0 + kk4 * 4);
        const float* wr = S.W + (size_t)(j0 + wml) * S.ldw + k0 + kh * 8;
        w4a = *(const float4*)(wr);
        w4b = *(const float4*)(wr + 4);
    };
    auto store = [&](int buf, const float4& a4, const float4& w4a, const float4& w4b) {
        int kb = kk4 * 4;
        sh.As[buf][kb + 0][ml] = a4.x;
        sh.As[buf][kb + 1][ml] = a4.y;
        sh.As[buf][kb + 2][ml] = a4.z;
        sh.As[buf][kb + 3][ml] = a4.w;
        int wb = kh * 8;
        sh.Ws[buf][wb + 0][wml] = w4a.x;
        sh.Ws[buf][wb + 1][wml] = w4a.y;
        sh.Ws[buf][wb + 2][wml] = w4a.z;
        sh.Ws[buf][wb + 3][wml] = w4a.w;
        sh.Ws[buf][wb + 4][wml] = w4b.x;
        sh.Ws[buf][wb + 5][wml] = w4b.y;
        sh.Ws[buf][wb + 6][wml] = w4b.z;
        sh.Ws[buf][wb + 7][wml] = w4b.w;
    };
    auto compute = [&](int buf) {
#pragma unroll
        for (int kk = 0; kk < 16; kk++) {
            const ulonglong2* ap = (const ulonglong2*)&sh.As[buf][kk][ty * 8];
            ulonglong2 a01 = ap[0];           // M pairs (m0,m1),(m2,m3)
            ulonglong2 a23 = ap[1];           // (m4,m5),(m6,m7)
            float4 w = *(const float4*)&sh.Ws[buf][kk][tx * 4];
            ull w0 = pack2(w.x, w.x), w1 = pack2(w.y, w.y);
            ull w2 = pack2(w.z, w.z), w3 = pack2(w.w, w.w);
            acc[0][0] = fma2(a01.x, w0, acc[0][0]); acc[0][1] = fma2(a01.x, w1, acc[0][1]);
            acc[0][2] = fma2(a01.x, w2, acc[0][2]); acc[0][3] = fma2(a01.x, w3, acc[0][3]);
            acc[1][0] = fma2(a01.y, w0, acc[1][0]); acc[1][1] = fma2(a01.y, w1, acc[1][1]);
            acc[1][2] = fma2(a01.y, w2, acc[1][2]); acc[1][3] = fma2(a01.y, w3, acc[1][3]);
            acc[2][0] = fma2(a23.x, w0, acc[2][0]); acc[2][1] = fma2(a23.x, w1, acc[2][1]);
            acc[2][2] = fma2(a23.x, w2, acc[2][2]); acc[2][3] = fma2(a23.x, w3, acc[2][3]);
            acc[3][0] = fma2(a23.y, w0, acc[3][0]); acc[3][1] = fma2(a23.y, w1, acc[3][1]);
            acc[3][2] = fma2(a23.y, w2, acc[3][2]); acc[3][3] = fma2(a23.y, w3, acc[3][3]);
        }
    };

    int nch = cend - cbeg;
    float4 Aa, Wa, Wa2;
    {
        float4 a, w, w2;
        fetch(cbeg, a, w, w2); store(0, a, w, w2);
        if (nch > 1) { fetch(cbeg + 1, a, w, w2); store(1, a, w, w2); }
    }
    __syncthreads();

    for (int i = 0; i < nch; i++) {
        bool more = (i + 2 < nch);
        if (more) fetch(cbeg + i + 2, Aa, Wa, Wa2);
        compute(i % 3);
        if (more) store((i + 2) % 3, Aa, Wa, Wa2);
        __syncthreads();
    }

#pragma unroll
    for (int mp = 0; mp < 4; mp++) {
        int m0 = ty * 8 + 2 * mp;
        float2 c0 = unpack2(acc[mp][0]);
        float2 c1 = unpack2(acc[mp][1]);
        float2 c2 = unpack2(acc[mp][2]);
        float2 c3 = unpack2(acc[mp][3]);
        *(float4*)(dst + (size_t)m0 * ldo + j0 + tx * 4) =
            make_float4(c0.x, c1.x, c2.x, c3.x);
        *(float4*)(dst + (size_t)(m0 + 1) * ldo + j0 + tx * 4) =
            make_float4(c0.y, c1.y, c2.y, c3.y);
    }
}

// ---------------- params ----------------
struct Params {
    const float *last_frame, *att_h, *att_c, *att_w, *att_w_cum, *att_ctx,
                *dec_h, *dec_c, *memory, *pm,
                *W_ih_a, *W_hh_a, *b_ih_a, *b_hh_a,
                *W_q, *W_v, *W_loc, *W_lfc,
                *W_ih_d, *W_hh_d, *b_ih_d, *b_hh_d,
                *W_proj, *b_proj, *W_gate, *b_gate;
    const void* mask;
    float *out, *stop_out, *w_out;
};

// ---------------- helper: LSTM pointwise over all elements ----------------
__device__ void lstm_phase(const float* part, int nsplit,
                           const float* b1, const float* b2,
                           const float* c_in, float* h_out, float* c_out, int gtid) {
    for (int idx = gtid; idx < BB * 1024; idx += NT) {
        int b = idx >> 10, r = idx & 1023;
        size_t base = (size_t)b * 4096;
        float g0 = b1[r]        + b2[r];
        float g1 = b1[1024 + r] + b2[1024 + r];
        float g2 = b1[2048 + r] + b2[2048 + r];
        float g3 = b1[3072 + r] + b2[3072 + r];
        for (int p = 0; p < nsplit; p++) {
            const float* pp = part + (size_t)p * BB * 4096 + base + r;
            g0 += pp[0];
            g1 += pp[1024];
            g2 += pp[2048];
            g3 += pp[3072];
        }
        float c  = c_in[idx];
        float c2 = sigfast(g1) * c + sigfast(g0) * tanhfast(g2);
        float h2 = sigfast(g3) * tanhfast(c2);
        c_out[idx] = c2;
        h_out[idx] = h2;
    }
}

// ---------------- the mono kernel (3 blocks/SM) ----------------
__global__ __launch_bounds__(NTHR, 3) void mono_k(Params p) {
    __shared__ SMemU sm;
    int tid = threadIdx.x;
    int bid = blockIdx.x;
    int gtid = bid * NTHR + tid;
    unsigned sense = 0, sense2 = 0;
    if (tid == 0) { sense = g_bar_sense; sense2 = g_bar2_sense; }

    // ================= Phase A: attention-gate GEMM (12-way splitK) ========
    if (bid < 384) {
        Seg sa[3] = {
            { p.last_frame, p.W_ih_a,      PP, PP + EE, PP },
            { p.att_ctx,    p.W_ih_a + PP, EE, PP + EE, EE },
            { p.att_h,      p.W_hh_a,      RR, RR,      RR }
        };
        int jt = bid & 31;
        int sp = bid >> 5;      // 0..11, 88 chunks -> 7-8 each
        int cb = (88 * sp) / 12;
        int ce = (88 * (sp + 1)) / 12;
        gemm_tile(sa, jt * 128, cb, ce,
                  g_part + (size_t)sp * BB * 4096, 4096, sm.ge);
    } else if (bid == 440) {
        const unsigned int* mw = (const unsigned int*)p.mask;
        int n01 = 0, nf = 0;
        for (int i = tid; i < 4096; i += NTHR) {
            unsigned v = mw[i];
            n01 |= (v > 1u);
            nf  |= (v != 0u && v != 0x3F800000u);
        }
        int a  = __syncthreads_or(n01);
        int bf = __syncthreads_or(nf);
        if (tid == 0) g_maskmode = a ? (bf ? 2 : 1) : 0;
    }
    gridbar(sense, bid);

    // ================= Phase B: attention LSTM pointwise ====================
    lstm_phase(g_part, 12, p.b_ih_a, p.b_hh_a, p.att_c, g_ah, g_ac, gtid);
    gridbar(sense, bid);

    // ================= Phase CD: decoder GEMM (K=2048)  ||  pq + energies ===
    if (bid < 192) {
        Seg sd[3] = {
            { g_ah,    p.W_ih_d, RR, RR + EE, RR },
            { p.dec_h, p.W_hh_d, DD, DD,      DD },
            { g_ah,    p.W_ih_d, RR, RR + EE, 0 }   // dummy
        };
        int jt = bid & 31;
        int sp = bid >> 5;      // 0..5, 128 chunks -> 21-22 each
        int cb = (128 * sp) / 6;
        int ce = (128 * (sp + 1)) / 6;
        gemm_tile(sd, jt * 128, cb, ce,
                  g_part + (size_t)sp * BB * 4096, 4096, sm.ge);
    } else {
        int lbid = bid - 192;   // 0..251
        // ---- pq: warp dots over the energies sub-grid ----
        {
            int wid = lbid * (NTHR / 32) + (tid >> 5);
            int lane = tid & 31;
            for (int j = wid; j < BB * AA; j += NEBLK * (NTHR / 32)) {
                int m = j >> 7, n = j & 127;
                const float4* a = (const float4*)(g_ah + (size_t)m * RR);
                const float4* w = (const float4*)(p.W_q + (size_t)n * RR);
                float s = 0.f;
#pragma unroll
                for (int i = 0; i < 8; i++) {
                    float4 x = a[lane + 32 * i];
                    float4 y = w[lane + 32 * i];
                    s += x.x * y.x + x.y * y.y + x.z * y.z + x.w * y.w;
                }
#pragma unroll
                for (int off = 16; off > 0; off >>= 1) s += __shfl_xor_sync(0xFFFFFFFFu, s, off);
                if (lane == 0) g_pq[j] = s;
            }
        }
        gridbar2(sense2, lbid);   // pq visible to all energies blocks

        // ---- energies: stage weights once, then steal jobs ----
        for (int i = tid; i < 2 * KK * 16; i += NTHR) {
            int c = i / (KK * 16);
            int r = i % (KK * 16);
            int k = r / 16, fp = r % 16;
            float lo = p.W_loc[(2 * fp + 0) * (2 * KK) + c * KK + k];
            float hi = p.W_loc[(2 * fp + 1) * (2 * KK) + c * KK + k];
            ((ull*)sm.en.wl2)[c * KK * 16 + k * 16 + fp] = pack2(lo, hi);
        }
        for (int i = tid; i < AA * 8; i += NTHR)
            ((ulonglong2*)sm.en.wlfc2)[i] = ((const ulonglong2*)p.W_lfc)[i];
        if (tid < AA) sm.en.wv[tid] = p.W_v[tid];
        int mm = g_maskmode;

        for (;;) {
            __syncthreads();
            if (tid == 0) sm.en.job = (int)atomicAdd(&g_job1, 1u);
            __syncthreads();
            int job = sm.en.job;
            if (job >= 512) break;
            int b = job >> 3, tc = job & 7;
            int t0 = tc * 256;
            int t = t0 + tid;
            for (int i = tid; i < 286; i += NTHR) {
                int gidx = t0 - PAD + i;
                bool inb = (gidx >= 0 && gidx < TT);
                sm.en.aw0[i] = inb ? p.att_w[(size_t)b * TT + gidx] : 0.f;
                sm.en.aw1[i] = inb ? p.att_w_cum[(size_t)b * TT + gidx] : 0.f;
            }
            if (tid < AA) sm.en.pq[tid] = g_pq[b * AA + tid];
            __syncthreads();

            ull locf2[16];
#pragma unroll
            for (int i = 0; i < 16; i++) locf2[i] = 0ull;
            for (int k = 0; k < KK; k++) {
                ull a0 = pack2(sm.en.aw0[tid + k], sm.en.aw0[tid + k]);
                ull a1 = pack2(sm.en.aw1[tid + k], sm.en.aw1[tid + k]);
#pragma unroll
                for (int i = 0; i < 8; i++) {
                    ulonglong2 w0 = sm.en.wl2[0][k][i];
                    ulonglong2 w1 = sm.en.wl2[1][k][i];
                    locf2[2 * i]     = fma2(a0, w0.x, locf2[2 * i]);
                    locf2[2 * i + 1] = fma2(a0, w0.y, locf2[2 * i + 1]);
                    locf2[2 * i]     = fma2(a1, w1.x, locf2[2 * i]);
                    locf2[2 * i + 1] = fma2(a1, w1.y, locf2[2 * i + 1]);
                }
            }

            const float4* pmrow4 = (const float4*)(p.pm + ((size_t)b * TT + t) * AA);
            float e = 0.f;
#pragma unroll 1
            for (int a = 0; a < AA; a += 4) {
                float4 pv = pmrow4[a >> 2];
#pragma unroll
                for (int half = 0; half < 2; half++) {
                    int aa = a + 2 * half;
                    float p0 = half ? pv.z : pv.x;
                    float p1 = half ? pv.w : pv.y;
                    ull ac0 = 0ull, ac1 = 0ull, ac2 = 0ull, ac3 = 0ull;
#pragma unroll
                    for (int i = 0; i < 8; i++) {
                        ulonglong2 w0 = sm.en.wlfc2[aa][i];
                        ulonglong2 w1 = sm.en.wlfc2[aa + 1][i];
                        ac0 = fma2(locf2[2 * i],     w0.x, ac0);
                        ac1 = fma2(locf2[2 * i + 1], w0.y, ac1);
                        ac2 = fma2(locf2[2 * i],     w1.x, ac2);
                        ac3 = fma2(locf2[2 * i + 1], w1.y, ac3);
                    }
                    float2 f0 = unpack2(ac0), f1 = unpack2(ac1);
                    float2 f2 = unpack2(ac2), f3 = unpack2(ac3);
                    float la0 = (f0.x + f0.y) + (f1.x + f1.y);
                    float la1 = (f2.x + f2.y) + (f3.x + f3.y);
                    float x0 = sm.en.pq[aa] + p0 + la0;
                    float x1 = sm.en.pq[aa + 1] + p1 + la1;
                    e += tanhfast(x0) * sm.en.wv[aa];
                    e += tanhfast(x1) * sm.en.wv[aa + 1];
                }
            }

            size_t mi = (size_t)b * TT + t;
            bool masked;
            if (mm == 0)      masked = (((const int*)p.mask)[mi] != 0);
            else if (mm == 1) masked = (((const float*)p.mask)[mi] != 0.f);
            else              masked = (((const unsigned char*)p.mask)[mi] != 0);
            e = masked ? NEG_INF : e;
            g_energy[mi] = e;

            sm.en.red[tid] = e; __syncthreads();
            for (int s = 128; s > 0; s >>= 1) {
                if (tid < s) sm.en.red[tid] = fmaxf(sm.en.red[tid], sm.en.red[tid + s]);
                __syncthreads();
            }
            float Mc = sm.en.red[0]; __syncthreads();
            sm.en.red[tid] = __expf(e - Mc); __syncthreads();
            for (int s = 128; s > 0; s >>= 1) {
                if (tid < s) sm.en.red[tid] += sm.en.red[tid + s];
                __syncthreads();
            }
            if (tid == 0) {
                g_bm[b * 8 + tc] = Mc;
                g_bs[b * 8 + tc] = sm.en.red[0];
            }
        }
    }
    gridbar(sense, bid);

    // ================= Phase E: context partials (work-stealing) ===========
    for (;;) {
        __syncthreads();
        if (tid == 0) sm.cx.job = (int)atomicAdd(&g_job2, 1u);
        __syncthreads();
        int job = sm.cx.job;
        if (job >= 512) break;
        int b = job >> 3, tc = job & 7;
        int t0 = tc * 256;
        float M = -3.0e38f;
#pragma unroll
        for (int c = 0; c < 8; c++) M = fmaxf(M, g_bm[b * 8 + c]);
        float S = 0.f;
#pragma unroll
        for (int c = 0; c < 8; c++) S += g_bs[b * 8 + c] * __expf(g_bm[b * 8 + c] - M);
        float inv = 1.0f / S;

        float w = __expf(g_energy[(size_t)b * TT + t0 + tid] - M) * inv;
        sm.cx.w[tid] = w;
        p.w_out[(size_t)b * TT + t0 + tid] = w;
        __syncthreads();

        int rr = tid >> 6;        // 0..3
        int ee = tid & 63;        // 0..63
        const ulonglong2* mbase =
            (const ulonglong2*)(p.memory + ((size_t)b * TT + t0) * EE) + ee;
        ull a01 = 0ull, a23 = 0ull;
#pragma unroll 4
        for (int i = 0; i < 64; i++) {
            int row = rr * 64 + i;
            float wv = sm.cx.w[row];
            ulonglong2 mv = mbase[(size_t)row * 64];
            ull wv2 = pack2(wv, wv);
            a01 = fma2(wv2, mv.x, a01);
            a23 = fma2(wv2, mv.y, a23);
        }
        __syncthreads();
        {
            float2 r0 = unpack2(a01), r1 = unpack2(a23);
            sm.cx.r4[tid] = make_float4(r0.x, r0.y, r1.x, r1.y);
        }
        __syncthreads();
        if (tid < 64) {
            float4 s0 = sm.cx.r4[tid], s1 = sm.cx.r4[tid + 64];
            float4 s2 = sm.cx.r4[tid + 128], s3 = sm.cx.r4[tid + 192];
            float4 s;
            s.x = (s0.x + s1.x) + (s2.x + s3.x);
            s.y = (s0.y + s1.y) + (s2.y + s3.y);
            s.z = (s0.z + s1.z) + (s2.z + s3.z);
            s.w = (s0.w + s1.w) + (s2.w + s3.w);
            *(float4*)&g_ctx_part[((size_t)b * 8 + tc) * EE + tid * 4] = s;
        }
    }
    gridbar(sense, bid);

    // ================= Phase F: context reduce =============================
    for (int idx = gtid; idx < BB * EE; idx += NT) {
        int b = idx >> 8, e = idx & 255;
        float s = 0.f;
#pragma unroll
        for (int q = 0; q < 8; q++) s += g_ctx_part[((size_t)b * 8 + q) * EE + e];
        g_ctx[idx] = s;
    }
    gridbar(sense, bid);

    // ================= Phase G3: ctx contribution to decoder gates =========
    if (bid < 64) {
        Seg sc[3] = {
            { g_ctx, p.W_ih_d + RR, EE, RR + EE, EE },
            { g_ctx, p.W_ih_d + RR, EE, RR + EE, 0 },   // dummy
            { g_ctx, p.W_ih_d + RR, EE, RR + EE, 0 }    // dummy
        };
        int jt = bid & 31;
        int sp = bid >> 5;      // 0..1; 16 chunks -> 8 each, slices 6,7
        gemm_tile(sc, jt * 128, sp * 8, sp * 8 + 8,
                  g_part + (size_t)(6 + sp) * BB * 4096, 4096, sm.ge);
    }
    gridbar(sense, bid);

    // ================= Phase H: decoder LSTM pointwise =====================
    lstm_phase(g_part, 8, p.b_ih_d, p.b_hh_d, p.dec_c, g_dh, g_dc, gtid);
    gridbar(sense, bid);

    // ================= Phase I: projection + stop heads + counter reset ====
    if (bid == 0 && tid == 0) { g_job1 = 0u; g_job2 = 0u; }
    {
        int wid = gtid >> 5, lane = gtid & 31;
        for (int j = wid; j < BB * HH + BB; j += NT / 32) {
            bool is_stop = (j >= BB * HH);
            int m, h;
            const float4* w;
            if (!is_stop) {
                m = j >> 8; h = j & 255;
                w = (const float4*)(p.W_proj + (size_t)h * (DD + EE));
            } else {
                m = j - BB * HH;
                h = 0;
                w = (const float4*)p.W_gate;
            }
            const float4* a1 = (const float4*)(g_dh + (size_t)m * DD);
            const float4* a2 = (const float4*)(g_ctx + (size_t)m * EE);
            float s = 0.f;
#pragma unroll
            for (int i = 0; i < 8; i++) {
                float4 x = a1[lane + 32 * i];
                float4 y = w[lane + 32 * i];
                s += x.x * y.x + x.y * y.y + x.z * y.z + x.w * y.w;
            }
#pragma unroll
            for (int i = 0; i < 2; i++) {
                float4 x = a2[lane + 32 * i];
                float4 y = w[256 + lane + 32 * i];
                s += x.x * y.x + x.y * y.y + x.z * y.z + x.w * y.w;
            }
#pragma unroll
            for (int off = 16; off > 0; off >>= 1) s += __shfl_xor_sync(0xFFFFFFFFu, s, off);
            if (lane == 0) {
                if (!is_stop) p.out[j] = s + p.b_proj[h];
                else          p.stop_out[m] = s + p.b_gate[0];
            }
        }
    }
}

// ---------------- launch ----------------
extern "C" void kernel_launch(void* const* d_in, const int* in_sizes, int n_in,
                              void* d_out, int out_size) {
    Params p;
    p.last_frame = (const float*)d_in[0];
    p.att_h      = (const float*)d_in[1];
    p.att_c      = (const float*)d_in[2];
    p.att_w      = (const float*)d_in[3];
    p.att_w_cum  = (const float*)d_in[4];
    p.att_ctx    = (const float*)d_in[5];
    p.dec_h      = (const float*)d_in[6];
    p.dec_c      = (const float*)d_in[7];
    p.memory     = (const float*)d_in[8];
    p.pm         = (const float*)d_in[9];
    p.W_ih_a     = (const float*)d_in[10];
    p.W_hh_a     = (const float*)d_in[11];
    p.b_ih_a     = (const float*)d_in[12];
    p.b_hh_a     = (const float*)d_in[13];
    p.W_q        = (const float*)d_in[14];
    p.W_v        = (const float*)d_in[15];
    p.W_loc      = (const float*)d_in[16];
    p.W_lfc      = (const float*)d_in[17];
    p.W_ih_d     = (const float*)d_in[18];
    p.W_hh_d     = (const float*)d_in[19];
    p.b_ih_d     = (const float*)d_in[20];
    p.b_hh_d     = (const float*)d_in[21];
    p.W_proj     = (const float*)d_in[22];
    p.b_proj     = (const float*)d_in[23];
    p.W_gate     = (const float*)d_in[24];
    p.b_gate     = (const float*)d_in[25];
    p.mask       = d_in[26];

    float* out = (float*)d_out;
    p.out      = out;
    p.stop_out = out + BB * HH;
    p.w_out    = out + BB * HH + BB;

    mono_k<<<NBLK, NTHR>>>(p);
}